// round 1
// baseline (speedup 1.0000x reference)
#include <cuda_runtime.h>
#include <math.h>

#define BATCH 2048
#define TT    2048
#define HH    25

// Fast sigmoid: 1/(1+e^-x) via MUFU.EX2 + MUFU.RCP. Absolute error ~1e-7.
__device__ __forceinline__ float sigf(float x) {
    return __fdividef(1.0f, 1.0f + __expf(-x));
}

// tanh via e^{-2|x|}: r = (1-e)/(1+e), sign restored. Absolute error stays
// ~1e-7 even for small |x| (cancellation only inflates *relative* error of a
// tiny result). Clamp avoids denormal/overflow paths.
__device__ __forceinline__ float tanh_acc(float x) {
    float a = fminf(fabsf(x), 15.0f);
    float e = __expf(-2.0f * a);
    float r = __fdividef(1.0f - e, 1.0f + e);
    return copysignf(r, x);
}

// One warp per batch sequence. Lane j (j<25) owns hidden unit j: its c_j, h_j,
// and the four recurrent weight rows (i,f,g,o) for unit j in registers
// (100 floats). Each timestep: broadcast all 25 h values by warp shuffle,
// 100 FFMA to form the 4 gate pre-activations, pointwise LSTM update, then a
// 5-shuffle butterfly reduction for the fused dense head (w_dense · h + b).
// Lanes 25..31 duplicate lane 24 (clamped index) and carry wd=0, so they are
// numerically inert but keep the warp convergent.
__global__ void __launch_bounds__(64, 7)
lstm_fused(const float* __restrict__ x,        // [B, T, 1]
           const float* __restrict__ w_ih,     // [4H, 1]
           const float* __restrict__ w_hh,     // [4H, H]
           const float* __restrict__ b_ih,     // [4H]
           const float* __restrict__ b_hh,     // [4H]
           const float* __restrict__ w_dense,  // [1, H]
           const float* __restrict__ b_dense,  // [1]
           float* __restrict__ out)            // [B, T, 1]
{
    const int gwarp = (int)((blockIdx.x * 64u + threadIdx.x) >> 5);  // batch index
    const int lane  = (int)(threadIdx.x & 31u);
    if (gwarp >= BATCH) return;
    const int j = (lane < HH) ? lane : (HH - 1);   // clamped hidden-unit index

    // ---- Load per-lane weights into registers (one-time) ----
    float Wi[HH], Wf[HH], Wg[HH], Wo[HH];
#pragma unroll
    for (int k = 0; k < HH; k++) {
        Wi[k] = w_hh[(0 * HH + j) * HH + k];
        Wf[k] = w_hh[(1 * HH + j) * HH + k];
        Wg[k] = w_hh[(2 * HH + j) * HH + k];
        Wo[k] = w_hh[(3 * HH + j) * HH + k];
    }
    const float ui = w_ih[0 * HH + j];
    const float uf = w_ih[1 * HH + j];
    const float ug = w_ih[2 * HH + j];
    const float uo = w_ih[3 * HH + j];
    const float bi = b_ih[0 * HH + j] + b_hh[0 * HH + j];
    const float bf = b_ih[1 * HH + j] + b_hh[1 * HH + j];
    const float bg = b_ih[2 * HH + j] + b_hh[2 * HH + j];
    const float bo = b_ih[3 * HH + j] + b_hh[3 * HH + j];
    const float wd = (lane < HH) ? w_dense[lane] : 0.0f;
    const float bd = b_dense[0];

    const float4* xb = reinterpret_cast<const float4*>(x)   + (size_t)gwarp * (TT / 4);
    float4*       ob = reinterpret_cast<float4*>(out)       + (size_t)gwarp * (TT / 4);

    float h = 0.0f, c = 0.0f;

    // Double-buffered float4 input stream: next chunk is in flight while the
    // current 4 timesteps compute (~1500 cycles of work hides any L2/DRAM lat).
    float4 xq = xb[0];

#pragma unroll 1
    for (int tb = 0; tb < TT / 4; tb++) {
        const int tn = (tb + 1 < TT / 4) ? (tb + 1) : tb;
        float4 xn = xb[tn];                       // prefetch next chunk

        float xs[4] = {xq.x, xq.y, xq.z, xq.w};
        float yv[4];

#pragma unroll
        for (int s = 0; s < 4; s++) {
            const float xv = xs[s];
            // gate pre-activations: x-projection (IN=1) + bias folded into init
            float ai = fmaf(xv, ui, bi);
            float af = fmaf(xv, uf, bf);
            float ag = fmaf(xv, ug, bg);
            float ao = fmaf(xv, uo, bo);

            // recurrent matvec: broadcast h_k across the warp, 4 FFMA per k
#pragma unroll
            for (int k = 0; k < HH; k++) {
                const float hk = __shfl_sync(0xffffffffu, h, k);
                ai = fmaf(hk, Wi[k], ai);
                af = fmaf(hk, Wf[k], af);
                ag = fmaf(hk, Wg[k], ag);
                ao = fmaf(hk, Wo[k], ao);
            }

            const float gi = sigf(ai);
            const float gf = sigf(af);
            const float gg = tanh_acc(ag);
            const float go = sigf(ao);
            c = fmaf(gf, c, gi * gg);
            h = go * tanh_acc(c);

            // fused dense head: y = w_dense . h + b_dense  (butterfly reduce;
            // lanes >= 25 contribute 0 via wd=0)
            float p = h * wd;
            p += __shfl_xor_sync(0xffffffffu, p, 16);
            p += __shfl_xor_sync(0xffffffffu, p, 8);
            p += __shfl_xor_sync(0xffffffffu, p, 4);
            p += __shfl_xor_sync(0xffffffffu, p, 2);
            p += __shfl_xor_sync(0xffffffffu, p, 1);
            yv[s] = p + bd;
        }

        if (lane == 0) {
            ob[tb] = make_float4(yv[0], yv[1], yv[2], yv[3]);
        }
        xq = xn;
    }
}

extern "C" void kernel_launch(void* const* d_in, const int* in_sizes, int n_in,
                              void* d_out, int out_size) {
    const float* x       = (const float*)d_in[0];
    const float* w_ih    = (const float*)d_in[1];
    const float* w_hh    = (const float*)d_in[2];
    const float* b_ih    = (const float*)d_in[3];
    const float* b_hh    = (const float*)d_in[4];
    const float* w_dense = (const float*)d_in[5];
    const float* b_dense = (const float*)d_in[6];
    float* out = (float*)d_out;

    // 1024 CTAs x 64 threads = 2048 warps = one warp per batch row.
    // launch_bounds(64,7) -> <=146 regs, 7 CTAs/SM -> 14 warps/SM, single wave.
    lstm_fused<<<BATCH / 2, 64>>>(x, w_ih, w_hh, b_ih, b_hh,
                                  w_dense, b_dense, out);
}

// round 2
// speedup vs baseline: 1.0513x; 1.0513x over previous
#include <cuda_runtime.h>
#include <math.h>

#define BATCH 2048
#define TT    2048
#define HH    25
#define NPAIR 13

typedef unsigned long long u64;

// Packed f32x2 FMA (Blackwell): two fp32 FMAs per instruction. Only reachable
// via PTX fma.rn.f32x2 (ptxas never auto-fuses).
__device__ __forceinline__ u64 ffma2(u64 a, u64 b, u64 c) {
    u64 d; asm("fma.rn.f32x2 %0, %1, %2, %3;" : "=l"(d) : "l"(a), "l"(b), "l"(c)); return d;
}
__device__ __forceinline__ u64 pk2(float lo, float hi) {
    u64 r; asm("mov.b64 %0, {%1, %2};" : "=l"(r) : "f"(lo), "f"(hi)); return r;
}
__device__ __forceinline__ float2 upk2(u64 a) {
    float2 r; asm("mov.b64 {%0, %1}, %2;" : "=f"(r.x), "=f"(r.y) : "l"(a)); return r;
}
__device__ __forceinline__ float ex2a(float x) { float r; asm("ex2.approx.f32 %0, %1;" : "=f"(r) : "f"(x)); return r; }
__device__ __forceinline__ float rcpa(float x) { float r; asm("rcp.approx.f32 %0, %1;" : "=f"(r) : "f"(x)); return r; }

#define LOG2E 1.44269504088896340736f

// sigmoid(x) = 1/(1+2^(-x*log2e)) : FMUL + MUFU.EX2 + FADD + MUFU.RCP
__device__ __forceinline__ float sig_f(float x) {
    return rcpa(1.0f + ex2a(-LOG2E * x));
}
// tanh(x) = 2*sigmoid(2x) - 1 : saturates correctly at +-1, no NaN for finite x
__device__ __forceinline__ float tanh_f(float x) {
    return fmaf(2.0f, rcpa(1.0f + ex2a(-2.0f * LOG2E * x)), -1.0f);
}

// One warp per sequence. Lane j owns hidden unit j; its 4 recurrent weight
// rows live in registers as 13 packed f32x2 pairs each (pair 12 hi-slot holds
// the gate bias, multiplied by a constant 1.0 that lanes >=25 maintain in the
// shared h slot). Each step: STS h -> syncwarp -> 13x LDS.64 (packed h pairs,
// warp-broadcast) -> 52 FFMA2 -> activations -> 5-shuffle dense reduction.
__global__ void __launch_bounds__(64, 7)
lstm_fused(const float* __restrict__ x,        // [B, T, 1]
           const float* __restrict__ w_ih,     // [4H, 1]
           const float* __restrict__ w_hh,     // [4H, H]
           const float* __restrict__ b_ih,     // [4H]
           const float* __restrict__ b_hh,     // [4H]
           const float* __restrict__ w_dense,  // [1, H]
           const float* __restrict__ b_dense,  // [1]
           float* __restrict__ out)            // [B, T, 1]
{
    __shared__ __align__(16) float hs[2][2][32];   // [buf][warp][lane]

    const int w     = (int)(threadIdx.x >> 5);
    const int lane  = (int)(threadIdx.x & 31u);
    const int gwarp = blockIdx.x * 2 + w;
    const int j = (lane < HH) ? lane : (HH - 1);   // clamped unit index

    // ---- per-lane weights: 4 gates x 13 packed pairs (104 regs) ----
    u64 W[4][NPAIR];
#pragma unroll
    for (int g = 0; g < 4; g++) {
        const float* row = w_hh + (g * HH + j) * HH;
#pragma unroll
        for (int p = 0; p < NPAIR - 1; p++)
            W[g][p] = pk2(row[2 * p], row[2 * p + 1]);
        // pair 12: (W[j][24], bias) -- paired with smem (h24, 1.0)
        W[g][NPAIR - 1] = pk2(row[24], b_ih[g * HH + j] + b_hh[g * HH + j]);
    }
    const float ui = w_ih[0 * HH + j], uf = w_ih[1 * HH + j];
    const float ug = w_ih[2 * HH + j], uo = w_ih[3 * HH + j];
    const float wd = (lane < HH) ? w_dense[lane] : 0.0f;
    const float bd = b_dense[0];

    const float4* xb   = reinterpret_cast<const float4*>(x) + (size_t)gwarp * (TT / 4);
    float*        orow = out + (size_t)gwarp * TT;

    volatile float* h0s = &hs[0][w][0];
    volatile float* h1s = &hs[1][w][0];
    const volatile u64* hp0 = (const volatile u64*)h0s;
    const volatile u64* hp1 = (const volatile u64*)h1s;

    // initial state h=0; lanes >=25 maintain the constant-1 slot (bias feed)
    h0s[lane] = (lane < HH) ? 0.0f : 1.0f;

    float h = 0.0f, c = 0.0f;
    float4 xq = xb[0];   // double-buffered x stream (1 LDG.128 per 4 steps)

#pragma unroll 1
    for (int tb = 0; tb < TT / 4; tb++) {
        const int tn = (tb + 1 < TT / 4) ? tb + 1 : tb;
        float4 xn = xb[tn];
        float xs[4] = {xq.x, xq.y, xq.z, xq.w};

#pragma unroll
        for (int s = 0; s < 4; s++) {
            const float xv = xs[s];
            const volatile u64* hr = (s & 1) ? hp1 : hp0;  // read buf = t&1
            volatile float*     hw = (s & 1) ? h0s : h1s;  // write buf = (t+1)&1

            __syncwarp();   // prev step's STS (and init) visible before reads

            u64 ai = 0ull, af = 0ull, ag = 0ull, ao = 0ull;
#pragma unroll
            for (int p = 0; p < NPAIR; p++) {
                const u64 hpv = hr[p];     // packed (h_{2p}, h_{2p+1}), broadcast
                ai = ffma2(hpv, W[0][p], ai);
                af = ffma2(hpv, W[1][p], af);
                ag = ffma2(hpv, W[2][p], ag);
                ao = ffma2(hpv, W[3][p], ao);
            }
            float2 vi = upk2(ai), vf = upk2(af), vg = upk2(ag), vo = upk2(ao);
            const float pi = fmaf(xv, ui, vi.x + vi.y);   // bias already inside
            const float pf = fmaf(xv, uf, vf.x + vf.y);
            const float pg = fmaf(xv, ug, vg.x + vg.y);
            const float po = fmaf(xv, uo, vo.x + vo.y);

            const float gi = sig_f(pi);
            const float gf = sig_f(pf);
            const float gg = tanh_f(pg);
            const float go = sig_f(po);
            c = fmaf(gf, c, gi * gg);
            h = go * tanh_f(c);

            hw[lane] = (lane < HH) ? h : 1.0f;   // publish h (+constant-1 slots)

            // fused dense head: y = wd . h + bd (lanes >=25 contribute 0)
            float pr = h * wd;
            pr += __shfl_xor_sync(0xffffffffu, pr, 16);
            pr += __shfl_xor_sync(0xffffffffu, pr, 8);
            pr += __shfl_xor_sync(0xffffffffu, pr, 4);
            pr += __shfl_xor_sync(0xffffffffu, pr, 2);
            pr += __shfl_xor_sync(0xffffffffu, pr, 1);
            if (lane == 0) orow[4 * tb + s] = pr + bd;
        }
        xq = xn;
    }
}

extern "C" void kernel_launch(void* const* d_in, const int* in_sizes, int n_in,
                              void* d_out, int out_size) {
    const float* x       = (const float*)d_in[0];
    const float* w_ih    = (const float*)d_in[1];
    const float* w_hh    = (const float*)d_in[2];
    const float* b_ih    = (const float*)d_in[3];
    const float* b_hh    = (const float*)d_in[4];
    const float* w_dense = (const float*)d_in[5];
    const float* b_dense = (const float*)d_in[6];
    float* out = (float*)d_out;

    // 1024 CTAs x 64 threads = one warp per sequence; 7 CTAs/SM -> 14 warps/SM,
    // single wave across 148 SMs.
    lstm_fused<<<BATCH / 2, 64>>>(x, w_ih, w_hh, b_ih, b_hh,
                                  w_dense, b_dense, out);
}

// round 4
// speedup vs baseline: 1.1028x; 1.0490x over previous
#include <cuda_runtime.h>
#include <math.h>

#define BATCH 2048
#define TT    2048
#define HH    25
#define NPAIR 13

typedef unsigned long long u64;

// Packed f32x2 FMA (Blackwell): two fp32 FMAs per instruction (PTX-only form).
__device__ __forceinline__ u64 ffma2(u64 a, u64 b, u64 c) {
    u64 d; asm("fma.rn.f32x2 %0, %1, %2, %3;" : "=l"(d) : "l"(a), "l"(b), "l"(c)); return d;
}
__device__ __forceinline__ u64 pk2(float lo, float hi) {
    u64 r; asm("mov.b64 %0, {%1, %2};" : "=l"(r) : "f"(lo), "f"(hi)); return r;
}
__device__ __forceinline__ float2 upk2(u64 a) {
    float2 r; asm("mov.b64 {%0, %1}, %2;" : "=f"(r.x), "=f"(r.y) : "l"(a)); return r;
}
__device__ __forceinline__ float ex2a(float x) { float r; asm("ex2.approx.f32 %0, %1;" : "=f"(r) : "f"(x)); return r; }
__device__ __forceinline__ float rcpa(float x) { float r; asm("rcp.approx.f32 %0, %1;" : "=f"(r) : "f"(x)); return r; }

#define LOG2E 1.44269504088896340736f

__device__ __forceinline__ float sig_f(float x) {      // 1/(1+2^(-x*log2e))
    return rcpa(1.0f + ex2a(-LOG2E * x));
}
__device__ __forceinline__ float tanh_f(float x) {     // 2*sigmoid(2x)-1
    return fmaf(2.0f, rcpa(1.0f + ex2a(-2.0f * LOG2E * x)), -1.0f);
}

// One warp per sequence; lane j owns hidden unit j. Recurrent weights live in
// registers as 13 packed f32x2 pairs per gate; pair 12's hi slot carries the
// gate bias, fed by a constant 1.0 kept in the hi half of shared pair 12.
//
// The h broadcast buffer is u64-typed END TO END (same-type stores and loads,
// no volatile): even lanes publish packed (h_2p, h_2p+1) pairs via STS.64,
// all lanes read back 13 broadcast LDS.64 next step. __syncwarp() provides
// the store->load ordering. The dense head for the PREVIOUS step's h runs
// its 5-shuffle butterfly concurrently with the current matvec (off the
// recurrence critical path) and stores one step delayed.
__global__ void __launch_bounds__(64, 7)
lstm_fused(const float* __restrict__ x,        // [B, T, 1]
           const float* __restrict__ w_ih,     // [4H, 1]
           const float* __restrict__ w_hh,     // [4H, H]
           const float* __restrict__ b_ih,     // [4H]
           const float* __restrict__ b_hh,     // [4H]
           const float* __restrict__ w_dense,  // [1, H]
           const float* __restrict__ b_dense,  // [1]
           float* __restrict__ out)            // [B, T, 1]
{
    __shared__ __align__(16) u64 hs[2][2][16];   // [buf][warp][pair]

    const int w     = (int)(threadIdx.x >> 5);
    const int lane  = (int)(threadIdx.x & 31u);
    const int gwarp = blockIdx.x * 2 + w;
    const int j = (lane < HH) ? lane : (HH - 1);

    // ---- per-lane weights: 4 gates x 13 packed pairs ----
    u64 W[4][NPAIR];
#pragma unroll
    for (int g = 0; g < 4; g++) {
        const float* row = w_hh + (g * HH + j) * HH;
#pragma unroll
        for (int p = 0; p < NPAIR - 1; p++)
            W[g][p] = pk2(row[2 * p], row[2 * p + 1]);
        W[g][NPAIR - 1] = pk2(row[24], b_ih[g * HH + j] + b_hh[g * HH + j]);
    }
    const float ui = w_ih[0 * HH + j], uf = w_ih[1 * HH + j];
    const float ug = w_ih[2 * HH + j], uo = w_ih[3 * HH + j];
    const float wd = (lane < HH) ? w_dense[lane] : 0.0f;
    const float bd = b_dense[0];

    const float4* xb   = reinterpret_cast<const float4*>(x) + (size_t)gwarp * (TT / 4);
    float*        orow = out + (size_t)gwarp * TT;

    u64* b0 = &hs[0][w][0];
    u64* b1 = &hs[1][w][0];

    // init buffer 0: h = 0, pair 12 hi = 1.0 (bias feed)
    if (lane < NPAIR)
        b0[lane] = (lane == NPAIR - 1) ? pk2(0.0f, 1.0f) : 0ull;
    __syncwarp();

    float h = 0.0f, c = 0.0f;
    float4 xq = xb[0];

#pragma unroll 1
    for (int tb = 0; tb < TT / 4; tb++) {
        const int tn = (tb + 1 < TT / 4) ? tb + 1 : tb;
        float4 xn = xb[tn];
        float xs[4] = {xq.x, xq.y, xq.z, xq.w};

#pragma unroll
        for (int s = 0; s < 4; s++) {
            const int gt = 4 * tb + s;
            const float xv = xs[s];
            const u64* hr = (gt & 1) ? b1 : b0;   // read buf = t&1
            u64*       hw = (gt & 1) ? b0 : b1;   // write buf = (t+1)&1

            // dense head for PREVIOUS h, overlapped with the matvec below
            float pr = h * wd;
            pr += __shfl_xor_sync(0xffffffffu, pr, 16);
            pr += __shfl_xor_sync(0xffffffffu, pr, 8);
            pr += __shfl_xor_sync(0xffffffffu, pr, 4);
            pr += __shfl_xor_sync(0xffffffffu, pr, 2);
            pr += __shfl_xor_sync(0xffffffffu, pr, 1);

            // recurrent matvec: 13 broadcast LDS.64 + 52 FFMA2
            u64 ai = 0ull, af = 0ull, ag = 0ull, ao = 0ull;
#pragma unroll
            for (int p = 0; p < NPAIR; p++) {
                const u64 hpv = hr[p];
                ai = ffma2(hpv, W[0][p], ai);
                af = ffma2(hpv, W[1][p], af);
                ag = ffma2(hpv, W[2][p], ag);
                ao = ffma2(hpv, W[3][p], ao);
            }
            float2 vi = upk2(ai), vf = upk2(af), vg = upk2(ag), vo = upk2(ao);
            const float pi = fmaf(xv, ui, vi.x + vi.y);   // bias already inside
            const float pf = fmaf(xv, uf, vf.x + vf.y);
            const float pg = fmaf(xv, ug, vg.x + vg.y);
            const float po = fmaf(xv, uo, vo.x + vo.y);

            const float gi = sig_f(pi);
            const float gf = sig_f(pf);
            const float gg = tanh_f(pg);
            const float go = sig_f(po);
            c = fmaf(gf, c, gi * gg);
            h = go * tanh_f(c);

            // publish h as packed pairs: even lanes 0..24 store (h_l, h_{l+1});
            // lane 24 stores (h_24, 1.0) to keep the bias feed alive.
            float hn = __shfl_down_sync(0xffffffffu, h, 1);
            if (lane == 24) hn = 1.0f;
            if ((lane & 1) == 0 && lane < 26)
                hw[lane >> 1] = pk2(h, hn);

            if (lane == 0 && gt > 0) orow[gt - 1] = pr + bd;  // y[t-1], delayed

            __syncwarp();   // order STS.64 before next step's LDS.64
        }
        xq = xn;
    }

    // final output element y[T-1]
    float pr = h * wd;
    pr += __shfl_xor_sync(0xffffffffu, pr, 16);
    pr += __shfl_xor_sync(0xffffffffu, pr, 8);
    pr += __shfl_xor_sync(0xffffffffu, pr, 4);
    pr += __shfl_xor_sync(0xffffffffu, pr, 2);
    pr += __shfl_xor_sync(0xffffffffu, pr, 1);
    if (lane == 0) orow[TT - 1] = pr + bd;
}

extern "C" void kernel_launch(void* const* d_in, const int* in_sizes, int n_in,
                              void* d_out, int out_size) {
    const float* x       = (const float*)d_in[0];
    const float* w_ih    = (const float*)d_in[1];
    const float* w_hh    = (const float*)d_in[2];
    const float* b_ih    = (const float*)d_in[3];
    const float* b_hh    = (const float*)d_in[4];
    const float* w_dense = (const float*)d_in[5];
    const float* b_dense = (const float*)d_in[6];
    float* out = (float*)d_out;

    // 1024 CTAs x 64 threads = one warp per sequence; 7 CTAs/SM -> 14 warps/SM,
    // single wave across 148 SMs.
    lstm_fused<<<BATCH / 2, 64>>>(x, w_ih, w_hh, b_ih, b_hh,
                                  w_dense, b_dense, out);
}